// round 12
// baseline (speedup 1.0000x reference)
#include <cuda_runtime.h>
#include <math.h>

#define N_NODES 20000
#define N_EDGES 100000

// Scratch (allowed: __device__ globals, no runtime allocation)
__device__ float g_UP[(size_t)N_NODES * 512];    // [n][c*128+u], c: 0=s,1=vx,2=vy,3=vz
// Pre-converted tf32 fragment-layout weights
__device__ float g_W3F[32768];   // w3/8:   [nt64][ks8][lane32][2]
__device__ float g_WSF[32768];   // Wos:    [nt16][ks32][lane32][2]
__device__ float g_WTF[16384];   // Wov top [nt16][ks16][lane32][2]
__device__ float g_WBF[16384];   // Wov bot [nt16][ks16][lane32][2]

#define INV_SQRT_MUL 0.08838834764831845f   // 1/sqrt(128)
#define SILU_NORM    1.6790390826f
#define K_A0 (0.7071067811865476f  * 0.0625f)   // PW_0E / sqrt(256)
#define K_B0 (0.40824829046386307f * 0.0625f)   // PW_0E*INV_SQRT3 / sqrt(256)
#define K_1  (0.7071067811865476f  * 0.0625f)   // PW_1O*INV_SQRT3 / sqrt(256)

#define OUT_STRIDE 520   // sOUT row stride (pad breaks STS bank conflicts)
#define TPW_STRIDE 516   // sTPW row stride (r*516 mod 32 distinct per r)

__device__ __forceinline__ float silu_act(float x) {
    return x * SILU_NORM / (1.0f + expf(-x));
}

__device__ __forceinline__ unsigned f2tf(float x) {
    unsigned u;
    asm("cvt.rna.tf32.f32 %0, %1;" : "=r"(u) : "f"(x));
    return u;
}
__device__ __forceinline__ float f2tf_f(float x) {
    return __uint_as_float(f2tf(x));
}

__device__ __forceinline__ void mma_tf32(float* c,
                                         unsigned a0, unsigned a1, unsigned a2, unsigned a3,
                                         unsigned b0, unsigned b1) {
    asm volatile("mma.sync.aligned.m16n8k8.row.col.f32.tf32.tf32.f32 "
                 "{%0,%1,%2,%3}, {%4,%5,%6,%7}, {%8,%9}, {%0,%1,%2,%3};"
                 : "+f"(c[0]), "+f"(c[1]), "+f"(c[2]), "+f"(c[3])
                 : "r"(a0), "r"(a1), "r"(a2), "r"(a3), "r"(b0), "r"(b1));
}

// ---------------------------------------------------------------------------
// K0: one-time weight -> tf32 fragment-layout conversion
// ---------------------------------------------------------------------------
__global__ void k_prep(const float* __restrict__ w3,
                       const float* __restrict__ Wos,
                       const float* __restrict__ Wov) {
    int tid = blockIdx.x * blockDim.x + threadIdx.x;
    int nth = gridDim.x * blockDim.x;
    for (int idx = tid; idx < 32768; idx += nth) {
        int k = idx >> 9, n = idx & 511;
        int nt = n >> 3, l = (n & 7)*4 + (k & 3), v = (k >> 2) & 1;
        g_W3F[(nt*8 + (k >> 3))*64 + l*2 + v] = f2tf_f(w3[idx] * 0.125f);
    }
    for (int idx = tid; idx < 32768; idx += nth) {
        int k = idx >> 7, n = idx & 127;
        int nt = n >> 3, l = (n & 7)*4 + (k & 3), v = (k >> 2) & 1;
        g_WSF[(nt*32 + (k >> 3))*64 + l*2 + v] = f2tf_f(Wos[idx]);
    }
    for (int idx = tid; idx < 16384; idx += nth) {
        int k = idx >> 7, n = idx & 127;
        int nt = n >> 3, l = (n & 7)*4 + (k & 3), v = (k >> 2) & 1;
        int a = (nt*16 + (k >> 3))*64 + l*2 + v;
        g_WTF[a] = f2tf_f(Wov[idx]);
        g_WBF[a] = f2tf_f(Wov[idx + 16384]);
    }
}

// ---------------------------------------------------------------------------
// K1: node up-projection (R7 scalar version).  16 nodes/block, 512 threads.
// ---------------------------------------------------------------------------
__global__ void __launch_bounds__(512) k_node_up(const float* __restrict__ nf,
                                                 const float* __restrict__ Wus,
                                                 const float* __restrict__ Wuv) {
    extern __shared__ float sm[];
    float* sWs = sm;            // 16384
    float* sWv = sm + 16384;    // 16384
    float* sA  = sm + 32768;    // 16*512 = 8192
    int tid = threadIdx.x;
    {
        const float4* src = (const float4*)Wus; float4* dst = (float4*)sWs;
        #pragma unroll
        for (int i = 0; i < 8; i++) dst[tid + i*512] = src[tid + i*512];
        src = (const float4*)Wuv; dst = (float4*)sWv;
        #pragma unroll
        for (int i = 0; i < 8; i++) dst[tid + i*512] = src[tid + i*512];
    }
    int n0 = blockIdx.x * 16;
    {
        const float4* src = (const float4*)(nf + (size_t)n0 * 512);
        float4* dst = (float4*)sA;
        #pragma unroll
        for (int i = 0; i < 4; i++) dst[tid + i*512] = src[tid + i*512];
    }
    __syncthreads();

    int w = tid & 127, g = tid >> 7;
    float acc[4][4];
    #pragma unroll
    for (int j = 0; j < 4; j++)
        #pragma unroll
        for (int c = 0; c < 4; c++) acc[j][c] = 0.f;

    for (int k = 0; k < 128; k += 4) {
        float ws[4], wv[4];
        #pragma unroll
        for (int kk = 0; kk < 4; kk++) { ws[kk] = sWs[(k+kk)*128 + w]; wv[kk] = sWv[(k+kk)*128 + w]; }
        #pragma unroll
        for (int j = 0; j < 4; j++) {
            int base = (g*4 + j) * 512;
            float4 sa = *(const float4*)&sA[base + k];
            acc[j][0] += sa.x*ws[0] + sa.y*ws[1] + sa.z*ws[2] + sa.w*ws[3];
            float4 va = *(const float4*)&sA[base + 128 + 3*k];
            float4 vb = *(const float4*)&sA[base + 128 + 3*k + 4];
            float4 vc = *(const float4*)&sA[base + 128 + 3*k + 8];
            acc[j][1] += va.x*wv[0] + va.w*wv[1] + vb.z*wv[2] + vc.y*wv[3];
            acc[j][2] += va.y*wv[0] + vb.x*wv[1] + vb.w*wv[2] + vc.z*wv[3];
            acc[j][3] += va.z*wv[0] + vb.y*wv[1] + vc.x*wv[2] + vc.w*wv[3];
        }
    }
    #pragma unroll
    for (int j = 0; j < 4; j++) {
        int n = n0 + g*4 + j;
        float* o = g_UP + (size_t)n * 512;
        o[w]       = acc[j][0] * INV_SQRT_MUL;
        o[128 + w] = acc[j][1] * INV_SQRT_MUL;
        o[256 + w] = acc[j][2] * INV_SQRT_MUL;
        o[384 + w] = acc[j][3] * INV_SQRT_MUL;
    }
}

// ---------------------------------------------------------------------------
// K3 v6 (FUSED): edge MLP + gather + elementwise + output GEMMs.
// 32 edges/block, 768 threads (24 warps).
// Phase 0a: scalar MLP hidden layers (threads 0-511, K2 partition).
// Phase 0b: tpw = h @ w3 via mma (warps 0-15) -> sTPW (smem, stride 516).
// Phase 1 : build A fragments (reads sTPW via LDS + g_UP gather).
// Phase 2 : 24 balanced 128-mma jobs -> sOUT (stride 520).
// Phase 3 : coalesced float4 copy-out.
// smem (floats):
//  Region A 0..24576: sA_S 0..8192 | sA_P 8192..12288 | sA_B 12288..24576
//    phase-0 aliases: sw0 0..512 | sw1 512..4608 | sw2 4608..8704 |
//                     sef 8704..8960 | hA 8960..11008 | hB 11008..13056 |
//                     sAf 13056..15104
//  meta 24576..24736 (sSh0, sSh1, sSnd)
//  Region B 24832..41472: sTPW (32x516, phases 0b-1) alias sOUT (32x520, 2-3)
// ---------------------------------------------------------------------------
__global__ void __launch_bounds__(768) k_edge_out(const float* __restrict__ eattr,
                                                  const int* __restrict__ eidx,
                                                  const float* __restrict__ ef,
                                                  const float* __restrict__ w0,
                                                  const float* __restrict__ w1,
                                                  const float* __restrict__ w2,
                                                  float* __restrict__ out) {
    extern __shared__ float sm[];
    float* sA_S = sm;
    float* sA_P = sm + 8192;
    float* sA_B = sm + 12288;
    // phase-0 aliases (inside region A)
    float* sw0 = sm;
    float* sw1 = sm + 512;
    float* sw2 = sm + 4608;
    float* sef = sm + 8704;
    float* hA  = sm + 8960;
    float* hB  = sm + 11008;
    float* sAf = sm + 13056;
    // meta
    float* sSh0 = sm + 24576;
    float* sSh1 = sm + 24608;
    int*   sSnd = (int*)(sm + 24704);
    // region B
    float* sTPW = sm + 24832;
    float* sOUT = sm + 24832;

    int tid = threadIdx.x;
    int wid = tid >> 5, lane = tid & 31;
    int e0 = blockIdx.x * 32;

    // Phase init: meta + MLP weights + edge feats
    if (tid < 32) {
        int e = e0 + tid;
        sSnd[tid] = eidx[e];
        sSh0[tid]     = eattr[(size_t)e*4 + 0];
        sSh1[tid*3+0] = eattr[(size_t)e*4 + 1];
        sSh1[tid*3+1] = eattr[(size_t)e*4 + 2];
        sSh1[tid*3+2] = eattr[(size_t)e*4 + 3];
    }
    if (tid < 512) sw0[tid] = w0[tid] * 0.35355339059327373f;   // 1/sqrt(8)
    for (int i = tid; i < 4096; i += 768) { sw1[i] = w1[i]*0.125f; sw2[i] = w2[i]*0.125f; }
    if (tid >= 512 && tid < 768) sef[tid - 512] = ef[(size_t)e0*8 + (tid - 512)];
    __syncthreads();

    // Phase 0a: scalar MLP hidden layers (threads 0-511; K2 partition)
    if (tid < 512) {
        int o = tid & 63, eg = tid >> 6;   // 8 groups x 4 edges
        #pragma unroll
        for (int j = 0; j < 4; j++) {       // layer 0, K=8
            int e = eg*4 + j;
            float a = 0.f;
            #pragma unroll
            for (int k = 0; k < 8; k++) a += sef[e*8+k] * sw0[k*64+o];
            hA[e*64+o] = silu_act(a);
        }
    }
    __syncthreads();
    if (tid < 512) {
        int o = tid & 63, eg = tid >> 6;
        #pragma unroll
        for (int j = 0; j < 4; j++) {       // layer 1
            int e = eg*4 + j;
            float a = 0.f;
            #pragma unroll
            for (int k = 0; k < 64; k += 4) {
                float4 x = *(const float4*)&hA[e*64+k];
                a += x.x*sw1[k*64+o] + x.y*sw1[(k+1)*64+o] + x.z*sw1[(k+2)*64+o] + x.w*sw1[(k+3)*64+o];
            }
            hB[e*64+o] = silu_act(a);
        }
    }
    __syncthreads();
    if (tid < 512) {
        int o = tid & 63, eg = tid >> 6;
        #pragma unroll
        for (int j = 0; j < 4; j++) {       // layer 2 -> A fragments
            int e = eg*4 + j;
            float a = 0.f;
            #pragma unroll
            for (int k = 0; k < 64; k += 4) {
                float4 x = *(const float4*)&hB[e*64+k];
                a += x.x*sw2[k*64+o] + x.y*sw2[(k+1)*64+o] + x.z*sw2[(k+2)*64+o] + x.w*sw2[(k+3)*64+o];
            }
            float val = silu_act(a);
            int strip = e >> 4, row = e & 15;
            int r = row & 7, hi = row >> 3;
            int ks = o >> 3, kr = o & 7;
            int l = r*4 + (kr & 3), v = hi + ((kr >> 2) << 1);
            sAf[(strip*8 + ks)*128 + l*4 + v] = f2tf_f(val);
        }
    }
    __syncthreads();

    // Phase 0b: tpw = h @ (w3/8) via mma (warps 0-15) -> sTPW
    if (wid < 16) {
        int strip = wid & 1, nb = (wid >> 1) * 8;
        float acc[8][4];
        #pragma unroll
        for (int t = 0; t < 8; t++)
            #pragma unroll
            for (int i = 0; i < 4; i++) acc[t][i] = 0.f;
        #pragma unroll
        for (int kk = 0; kk < 8; kk++) {
            float4 af = *(const float4*)(sAf + (strip*8 + kk)*128 + lane*4);
            unsigned a0 = __float_as_uint(af.x), a1 = __float_as_uint(af.y);
            unsigned a2 = __float_as_uint(af.z), a3 = __float_as_uint(af.w);
            #pragma unroll
            for (int t = 0; t < 8; t++) {
                float2 bf = *(const float2*)(g_W3F + ((nb + t)*8 + kk)*64 + lane*2);
                mma_tf32(acc[t], a0, a1, a2, a3, __float_as_uint(bf.x), __float_as_uint(bf.y));
            }
        }
        int r = lane >> 2, c2 = (lane & 3) * 2;
        #pragma unroll
        for (int t = 0; t < 8; t++) {
            int col = (nb + t)*8 + c2;
            int el = strip*16 + r;
            *(float2*)&sTPW[el*TPW_STRIDE + col]     = make_float2(acc[t][0], acc[t][1]);
            *(float2*)&sTPW[(el+8)*TPW_STRIDE + col] = make_float2(acc[t][2], acc[t][3]);
        }
    }
    __syncthreads();

    // Phase 1: build A fragments (overwrites region A; sTPW read via LDS)
    for (int idx = tid; idx < 4096; idx += 768) {
        int el = idx >> 7, u = idx & 127;
        const float* up = g_UP + (size_t)sSnd[el] * 512;
        float ss = up[u];
        float vx = up[128+u], vy = up[256+u], vz = up[384+u];
        const float* tp = sTPW + el*TPW_STRIDE;
        float w00 = tp[u], w01 = tp[128+u], w10 = tp[256+u], w11 = tp[384+u];
        float sh0 = sSh0[el];
        float h1x = sSh1[el*3+0], h1y = sSh1[el*3+1], h1z = sSh1[el*3+2];

        float a0v = K_A0 * w00 * ss * sh0;
        float b0v = K_B0 * w11 * (vx*h1x + vy*h1y + vz*h1z);
        float pv  = K_1  * w01 * ss;
        float t   = K_1  * w10 * sh0;

        int strip = el >> 4, row = el & 15;
        int r = row & 7, hi = row >> 3;
        int ks = u >> 3, kr = u & 7;
        int l = r*4 + (kr & 3), v = hi + ((kr >> 2) << 1);
        int off = l*4 + v;

        sA_S[(strip*32 + ks)*128 + off]        = f2tf_f(a0v);
        sA_S[(strip*32 + ks + 16)*128 + off]   = f2tf_f(b0v);
        sA_P[(strip*16 + ks)*128 + off]        = f2tf_f(pv);
        int bb = (strip*16 + ks)*128 + off;
        sA_B[bb]        = f2tf_f(t*vx);
        sA_B[bb + 4096] = f2tf_f(t*vy);
        sA_B[bb + 8192] = f2tf_f(t*vz);
    }
    __syncthreads();

    int r = lane >> 2, c2 = (lane & 3)*2;

    if (wid < 8) {
        // ---- S job: both strips, n-tiles {2*wid, 2*wid+1}, K=256 ----
        int np = wid;
        float acc[2][2][4];   // [strip][t][frag]
        #pragma unroll
        for (int s = 0; s < 2; s++)
            #pragma unroll
            for (int t = 0; t < 2; t++)
                #pragma unroll
                for (int i = 0; i < 4; i++) acc[s][t][i] = 0.f;

        #pragma unroll 4
        for (int k = 0; k < 32; k++) {
            float4 a0f = *(const float4*)(sA_S + k*128 + lane*4);          // strip 0
            float4 a1f = *(const float4*)(sA_S + (32 + k)*128 + lane*4);   // strip 1
            unsigned s0a = __float_as_uint(a0f.x), s0b = __float_as_uint(a0f.y);
            unsigned s0c = __float_as_uint(a0f.z), s0d = __float_as_uint(a0f.w);
            unsigned s1a = __float_as_uint(a1f.x), s1b = __float_as_uint(a1f.y);
            unsigned s1c = __float_as_uint(a1f.z), s1d = __float_as_uint(a1f.w);
            #pragma unroll
            for (int t = 0; t < 2; t++) {
                float2 bf = *(const float2*)(g_WSF + ((np*2 + t)*32 + k)*64 + lane*2);
                unsigned b0 = __float_as_uint(bf.x), b1 = __float_as_uint(bf.y);
                mma_tf32(acc[0][t], s0a, s0b, s0c, s0d, b0, b1);
                mma_tf32(acc[1][t], s1a, s1b, s1c, s1d, b0, b1);
            }
        }
        #pragma unroll
        for (int s = 0; s < 2; s++)
            #pragma unroll
            for (int t = 0; t < 2; t++) {
                int col = (np*2 + t)*8 + c2;
                int el = s*16 + r;
                *(float2*)&sOUT[el*OUT_STRIDE + col]     = make_float2(acc[s][t][0], acc[s][t][1]);
                *(float2*)&sOUT[(el+8)*OUT_STRIDE + col] = make_float2(acc[s][t][2], acc[s][t][3]);
            }
    } else {
        // ---- V job: P + Bx + By + Bz over 2 n-tiles, K=128 (16 ksteps) ----
        int j = wid - 8;
        int strip = j >> 3, np = j & 7;
        const float* ApP = sA_P + strip*16*128;
        const float* ApB = sA_B + strip*16*128;
        float aP[2][4], aX[2][4], aY[2][4], aZ[2][4];
        #pragma unroll
        for (int t = 0; t < 2; t++)
            #pragma unroll
            for (int i = 0; i < 4; i++) { aP[t][i]=0.f; aX[t][i]=0.f; aY[t][i]=0.f; aZ[t][i]=0.f; }

        #pragma unroll 4
        for (int k = 0; k < 16; k++) {
            float4 fP = *(const float4*)(ApP + k*128 + lane*4);
            float4 fX = *(const float4*)(ApB + k*128 + lane*4);
            float4 fY = *(const float4*)(ApB + 4096 + k*128 + lane*4);
            float4 fZ = *(const float4*)(ApB + 8192 + k*128 + lane*4);
            #pragma unroll
            for (int t = 0; t < 2; t++) {
                int nt = np*2 + t;
                float2 bT = *(const float2*)(g_WTF + (nt*16 + k)*64 + lane*2);
                float2 bB = *(const float2*)(g_WBF + (nt*16 + k)*64 + lane*2);
                unsigned bT0 = __float_as_uint(bT.x), bT1 = __float_as_uint(bT.y);
                unsigned bB0 = __float_as_uint(bB.x), bB1 = __float_as_uint(bB.y);
                mma_tf32(aP[t], __float_as_uint(fP.x), __float_as_uint(fP.y),
                                __float_as_uint(fP.z), __float_as_uint(fP.w), bT0, bT1);
                mma_tf32(aX[t], __float_as_uint(fX.x), __float_as_uint(fX.y),
                                __float_as_uint(fX.z), __float_as_uint(fX.w), bB0, bB1);
                mma_tf32(aY[t], __float_as_uint(fY.x), __float_as_uint(fY.y),
                                __float_as_uint(fY.z), __float_as_uint(fY.w), bB0, bB1);
                mma_tf32(aZ[t], __float_as_uint(fZ.x), __float_as_uint(fZ.y),
                                __float_as_uint(fZ.z), __float_as_uint(fZ.w), bB0, bB1);
            }
        }
        // recombine in registers, stage into sOUT: [el][128 + 3*col + i]
        #pragma unroll
        for (int t = 0; t < 2; t++) {
            int col = (np*2 + t)*8 + c2;
            #pragma unroll
            for (int half = 0; half < 2; half++) {
                int el = strip*16 + r + half*8;
                float shx = sSh1[el*3+0], shy = sSh1[el*3+1], shz = sSh1[el*3+2];
                float Q0 = aP[t][half*2], Q1 = aP[t][half*2+1];
                float X0 = aX[t][half*2], X1 = aX[t][half*2+1];
                float Y0 = aY[t][half*2], Y1 = aY[t][half*2+1];
                float Z0 = aZ[t][half*2], Z1 = aZ[t][half*2+1];
                float* o = sOUT + el*OUT_STRIDE + 128 + 3*col;
                *(float2*)(o)     = make_float2(Q0*shx + X0, Q0*shy + Y0);
                *(float2*)(o + 2) = make_float2(Q0*shz + Z0, Q1*shx + X1);
                *(float2*)(o + 4) = make_float2(Q1*shy + Y1, Q1*shz + Z1);
            }
        }
    }
    __syncthreads();

    // Phase 3: coalesced copy-out, 4096 float4s
    for (int idx = tid; idx < 4096; idx += 768) {
        int el = idx >> 7, q = idx & 127;
        float4 v = *(const float4*)&sOUT[el*OUT_STRIDE + q*4];
        *(float4*)&out[(size_t)(e0 + el)*512 + q*4] = v;
    }
}

// ---------------------------------------------------------------------------
extern "C" void kernel_launch(void* const* d_in, const int* in_sizes, int n_in,
                              void* d_out, int out_size) {
    const float* nf    = (const float*)d_in[0];
    const float* eattr = (const float*)d_in[1];
    const float* ef    = (const float*)d_in[2];
    const int*   eidx  = (const int*)d_in[3];
    const float* Wus   = (const float*)d_in[4];
    const float* Wuv   = (const float*)d_in[5];
    const float* w0    = (const float*)d_in[6];
    const float* w1    = (const float*)d_in[7];
    const float* w2    = (const float*)d_in[8];
    const float* w3    = (const float*)d_in[9];
    const float* Wos   = (const float*)d_in[10];
    const float* Wov   = (const float*)d_in[11];
    float* out = (float*)d_out;

    const size_t smem1 = 40960 * 4;   // 160KB
    const size_t smem3 = 41472 * 4;   // ~162KB
    cudaFuncSetAttribute(k_node_up, cudaFuncAttributeMaxDynamicSharedMemorySize, (int)smem1);
    cudaFuncSetAttribute(k_edge_out, cudaFuncAttributeMaxDynamicSharedMemorySize, (int)smem3);

    k_prep    <<<64, 512>>>(w3, Wos, Wov);
    k_node_up <<<N_NODES/16, 512, smem1>>>(nf, Wus, Wuv);
    k_edge_out<<<N_EDGES/32, 768, smem3>>>(eattr, eidx, ef, w0, w1, w2, out);
}

// round 14
// speedup vs baseline: 1.1697x; 1.1697x over previous
#include <cuda_runtime.h>
#include <math.h>

#define N_NODES 20000
#define N_EDGES 100000

// Scratch (allowed: __device__ globals, no runtime allocation)
__device__ float g_UP[(size_t)N_NODES * 512];    // [n][c*128+u], c: 0=s,1=vx,2=vy,3=vz
__device__ float g_TPW[(size_t)N_EDGES * 512];   // [e][512]
// Pre-converted tf32 fragment-layout weights
__device__ float g_W0F[512];     // w0/sqrt(8):  [nt8][ks1][lane32][2]
__device__ float g_W1F[4096];    // w1/8:        [nt8][ks8][lane32][2]
__device__ float g_W2F[4096];    // w2/8:        [nt8][ks8][lane32][2]
__device__ float g_W3F[32768];   // w3/8:        [nt64][ks8][lane32][2]
__device__ float g_WSF[32768];   // Wos:         [nt16][ks32][lane32][2]
__device__ float g_WTF[16384];   // Wov top      [nt16][ks16][lane32][2]
__device__ float g_WBF[16384];   // Wov bot      [nt16][ks16][lane32][2]

#define INV_SQRT_MUL 0.08838834764831845f   // 1/sqrt(128)
#define SILU_NORM    1.6790390826f
#define K_A0 (0.7071067811865476f  * 0.0625f)   // PW_0E / sqrt(256)
#define K_B0 (0.40824829046386307f * 0.0625f)   // PW_0E*INV_SQRT3 / sqrt(256)
#define K_1  (0.7071067811865476f  * 0.0625f)   // PW_1O*INV_SQRT3 / sqrt(256)

#define OUT_STRIDE 520   // sOUT row stride (pad breaks STS bank conflicts)

__device__ __forceinline__ float silu_act(float x) {
    return x * SILU_NORM / (1.0f + expf(-x));
}

__device__ __forceinline__ unsigned f2tf(float x) {
    unsigned u;
    asm("cvt.rna.tf32.f32 %0, %1;" : "=r"(u) : "f"(x));
    return u;
}
__device__ __forceinline__ float f2tf_f(float x) {
    return __uint_as_float(f2tf(x));
}

__device__ __forceinline__ void mma_tf32(float* c,
                                         unsigned a0, unsigned a1, unsigned a2, unsigned a3,
                                         unsigned b0, unsigned b1) {
    asm volatile("mma.sync.aligned.m16n8k8.row.col.f32.tf32.tf32.f32 "
                 "{%0,%1,%2,%3}, {%4,%5,%6,%7}, {%8,%9}, {%0,%1,%2,%3};"
                 : "+f"(c[0]), "+f"(c[1]), "+f"(c[2]), "+f"(c[3])
                 : "r"(a0), "r"(a1), "r"(a2), "r"(a3), "r"(b0), "r"(b1));
}

// silu(C-frag) -> A-fragment-layout smem store.
// Element (rowInStrip, k): addr = (strip*8 + nt)*128 + (r*4 + (k&3))*4 + (hi + ((k>>2&1)<<1))
__device__ __forceinline__ void silu_store_frag(float* buf, int strip, int nt,
                                                int r, int c2, const float* c) {
    int base = (strip*8 + nt)*128;
    int b2 = ((c2 >> 2) & 1) << 1;
    int la = r*4 + (c2 & 3);
    buf[base + la*4 + b2]           = f2tf_f(silu_act(c[0]));
    buf[base + (la+1)*4 + b2]       = f2tf_f(silu_act(c[1]));
    buf[base + la*4 + 1 + b2]       = f2tf_f(silu_act(c[2]));
    buf[base + (la+1)*4 + 1 + b2]   = f2tf_f(silu_act(c[3]));
}

// ---------------------------------------------------------------------------
// K0: one-time weight -> tf32 fragment-layout conversion
// ---------------------------------------------------------------------------
__global__ void k_prep(const float* __restrict__ w0,
                       const float* __restrict__ w1,
                       const float* __restrict__ w2,
                       const float* __restrict__ w3,
                       const float* __restrict__ Wos,
                       const float* __restrict__ Wov) {
    int tid = blockIdx.x * blockDim.x + threadIdx.x;
    int nth = gridDim.x * blockDim.x;
    for (int idx = tid; idx < 512; idx += nth) {
        int k = idx >> 6, n = idx & 63;
        int nt = n >> 3, l = (n & 7)*4 + (k & 3), v = (k >> 2) & 1;
        g_W0F[nt*64 + l*2 + v] = f2tf_f(w0[idx] * 0.35355339059327373f);
    }
    for (int idx = tid; idx < 4096; idx += nth) {
        int k = idx >> 6, n = idx & 63;
        int nt = n >> 3, l = (n & 7)*4 + (k & 3), v = (k >> 2) & 1;
        int a = (nt*8 + (k >> 3))*64 + l*2 + v;
        g_W1F[a] = f2tf_f(w1[idx] * 0.125f);
        g_W2F[a] = f2tf_f(w2[idx] * 0.125f);
    }
    for (int idx = tid; idx < 32768; idx += nth) {
        int k = idx >> 9, n = idx & 511;
        int nt = n >> 3, l = (n & 7)*4 + (k & 3), v = (k >> 2) & 1;
        g_W3F[(nt*8 + (k >> 3))*64 + l*2 + v] = f2tf_f(w3[idx] * 0.125f);
    }
    for (int idx = tid; idx < 32768; idx += nth) {
        int k = idx >> 7, n = idx & 127;
        int nt = n >> 3, l = (n & 7)*4 + (k & 3), v = (k >> 2) & 1;
        g_WSF[(nt*32 + (k >> 3))*64 + l*2 + v] = f2tf_f(Wos[idx]);
    }
    for (int idx = tid; idx < 16384; idx += nth) {
        int k = idx >> 7, n = idx & 127;
        int nt = n >> 3, l = (n & 7)*4 + (k & 3), v = (k >> 2) & 1;
        int a = (nt*16 + (k >> 3))*64 + l*2 + v;
        g_WTF[a] = f2tf_f(Wov[idx]);
        g_WBF[a] = f2tf_f(Wov[idx + 16384]);
    }
}

// ---------------------------------------------------------------------------
// K1: node up-projection (R7 scalar version).  16 nodes/block, 512 threads.
// ---------------------------------------------------------------------------
__global__ void __launch_bounds__(512) k_node_up(const float* __restrict__ nf,
                                                 const float* __restrict__ Wus,
                                                 const float* __restrict__ Wuv) {
    extern __shared__ float sm[];
    float* sWs = sm;            // 16384
    float* sWv = sm + 16384;    // 16384
    float* sA  = sm + 32768;    // 16*512 = 8192
    int tid = threadIdx.x;
    {
        const float4* src = (const float4*)Wus; float4* dst = (float4*)sWs;
        #pragma unroll
        for (int i = 0; i < 8; i++) dst[tid + i*512] = src[tid + i*512];
        src = (const float4*)Wuv; dst = (float4*)sWv;
        #pragma unroll
        for (int i = 0; i < 8; i++) dst[tid + i*512] = src[tid + i*512];
    }
    int n0 = blockIdx.x * 16;
    {
        const float4* src = (const float4*)(nf + (size_t)n0 * 512);
        float4* dst = (float4*)sA;
        #pragma unroll
        for (int i = 0; i < 4; i++) dst[tid + i*512] = src[tid + i*512];
    }
    __syncthreads();

    int w = tid & 127, g = tid >> 7;
    float acc[4][4];
    #pragma unroll
    for (int j = 0; j < 4; j++)
        #pragma unroll
        for (int c = 0; c < 4; c++) acc[j][c] = 0.f;

    for (int k = 0; k < 128; k += 4) {
        float ws[4], wv[4];
        #pragma unroll
        for (int kk = 0; kk < 4; kk++) { ws[kk] = sWs[(k+kk)*128 + w]; wv[kk] = sWv[(k+kk)*128 + w]; }
        #pragma unroll
        for (int j = 0; j < 4; j++) {
            int base = (g*4 + j) * 512;
            float4 sa = *(const float4*)&sA[base + k];
            acc[j][0] += sa.x*ws[0] + sa.y*ws[1] + sa.z*ws[2] + sa.w*ws[3];
            float4 va = *(const float4*)&sA[base + 128 + 3*k];
            float4 vb = *(const float4*)&sA[base + 128 + 3*k + 4];
            float4 vc = *(const float4*)&sA[base + 128 + 3*k + 8];
            acc[j][1] += va.x*wv[0] + va.w*wv[1] + vb.z*wv[2] + vc.y*wv[3];
            acc[j][2] += va.y*wv[0] + vb.x*wv[1] + vb.w*wv[2] + vc.z*wv[3];
            acc[j][3] += va.z*wv[0] + vb.y*wv[1] + vc.x*wv[2] + vc.w*wv[3];
        }
    }
    #pragma unroll
    for (int j = 0; j < 4; j++) {
        int n = n0 + g*4 + j;
        float* o = g_UP + (size_t)n * 512;
        o[w]       = acc[j][0] * INV_SQRT_MUL;
        o[128 + w] = acc[j][1] * INV_SQRT_MUL;
        o[256 + w] = acc[j][2] * INV_SQRT_MUL;
        o[384 + w] = acc[j][3] * INV_SQRT_MUL;
    }
}

// ---------------------------------------------------------------------------
// K2 v2: edge MLP fully on tensor cores. 32 edges/block, 512 threads (16 warps).
// All layers tf32 mma; silu applied on C-frags, stored back in A-frag layout.
// Jobs per layer: (strip = wid&1, nt = wid>>1). Final: (strip, 8 n-tiles).
// smem static ~17KB -> 3 CTAs/SM.
// ---------------------------------------------------------------------------
__global__ void __launch_bounds__(512) k_edge_mlp(const float* __restrict__ ef) {
    __shared__ float sF0[256];     // layer-0 A frags (K=8: 1 kstep, 2 strips)
    __shared__ float bufA[2048];   // [strip2][ks8][128]
    __shared__ float bufB[2048];
    int tid = threadIdx.x;
    int wid = tid >> 5, lane = tid & 31;
    int e0 = blockIdx.x * 32;

    // Build layer-0 A fragments straight from ef
    if (tid < 256) {
        float val = ef[(size_t)e0*8 + tid];
        int el = tid >> 3, k = tid & 7;
        int strip = el >> 4, row = el & 15;
        int r = row & 7, hi = row >> 3;
        int l = r*4 + (k & 3), v = hi + ((k >> 2) << 1);
        sF0[strip*128 + l*4 + v] = f2tf_f(val);
    }
    __syncthreads();

    int strip = wid & 1, nt = wid >> 1;
    int r = lane >> 2, c2 = (lane & 3)*2;

    // Layer 0: (32x8)@(8x64), 1 mma per warp -> bufA
    {
        float c[4] = {0.f, 0.f, 0.f, 0.f};
        float4 af = *(const float4*)(sF0 + strip*128 + lane*4);
        float2 bf = *(const float2*)(g_W0F + nt*64 + lane*2);
        mma_tf32(c, __float_as_uint(af.x), __float_as_uint(af.y),
                    __float_as_uint(af.z), __float_as_uint(af.w),
                    __float_as_uint(bf.x), __float_as_uint(bf.y));
        silu_store_frag(bufA, strip, nt, r, c2, c);
    }
    __syncthreads();

    // Layer 1: (32x64)@(64x64), 8 mmas per warp, bufA -> bufB
    {
        float c[4] = {0.f, 0.f, 0.f, 0.f};
        #pragma unroll
        for (int ks = 0; ks < 8; ks++) {
            float4 af = *(const float4*)(bufA + (strip*8 + ks)*128 + lane*4);
            float2 bf = *(const float2*)(g_W1F + (nt*8 + ks)*64 + lane*2);
            mma_tf32(c, __float_as_uint(af.x), __float_as_uint(af.y),
                        __float_as_uint(af.z), __float_as_uint(af.w),
                        __float_as_uint(bf.x), __float_as_uint(bf.y));
        }
        silu_store_frag(bufB, strip, nt, r, c2, c);
    }
    __syncthreads();

    // Layer 2: bufB -> bufA
    {
        float c[4] = {0.f, 0.f, 0.f, 0.f};
        #pragma unroll
        for (int ks = 0; ks < 8; ks++) {
            float4 af = *(const float4*)(bufB + (strip*8 + ks)*128 + lane*4);
            float2 bf = *(const float2*)(g_W2F + (nt*8 + ks)*64 + lane*2);
            mma_tf32(c, __float_as_uint(af.x), __float_as_uint(af.y),
                        __float_as_uint(af.z), __float_as_uint(af.w),
                        __float_as_uint(bf.x), __float_as_uint(bf.y));
        }
        silu_store_frag(bufA, strip, nt, r, c2, c);
    }
    __syncthreads();

    // Final: tpw = h @ (w3/8); 16 warps: (strip, 8 n-tiles of 64) -> g_TPW
    {
        int nb = (wid >> 1) * 8;
        float acc[8][4];
        #pragma unroll
        for (int t = 0; t < 8; t++)
            #pragma unroll
            for (int i = 0; i < 4; i++) acc[t][i] = 0.f;
        #pragma unroll
        for (int kk = 0; kk < 8; kk++) {
            float4 af = *(const float4*)(bufA + (strip*8 + kk)*128 + lane*4);
            unsigned a0 = __float_as_uint(af.x), a1 = __float_as_uint(af.y);
            unsigned a2 = __float_as_uint(af.z), a3 = __float_as_uint(af.w);
            #pragma unroll
            for (int t = 0; t < 8; t++) {
                float2 bf = *(const float2*)(g_W3F + ((nb + t)*8 + kk)*64 + lane*2);
                mma_tf32(acc[t], a0, a1, a2, a3, __float_as_uint(bf.x), __float_as_uint(bf.y));
            }
        }
        #pragma unroll
        for (int t = 0; t < 8; t++) {
            int col = (nb + t)*8 + c2;
            size_t eA = (size_t)(e0 + strip*16 + r);
            *(float2*)&g_TPW[eA*512 + col]     = make_float2(acc[t][0], acc[t][1]);
            *(float2*)&g_TPW[(eA+8)*512 + col] = make_float2(acc[t][2], acc[t][3]);
        }
    }
}

// ---------------------------------------------------------------------------
// K3 (R11 version): 32 edges/block, 768 threads (24 warps), 24 balanced
// 128-mma jobs; results staged in sOUT then coalesced float4 copy-out.
// ---------------------------------------------------------------------------
__global__ void __launch_bounds__(768) k_edge_out(const float* __restrict__ eattr,
                                                  const int* __restrict__ eidx,
                                                  float* __restrict__ out) {
    extern __shared__ float sm[];
    float* sA_S = sm;
    float* sA_P = sm + 8192;
    float* sA_B = sm + 12288;
    float* sSh0 = sm + 24576;
    float* sSh1 = sm + 24608;
    int*   sSnd = (int*)(sm + 24704);
    float* sOUT = sm + 24832;   // 32 rows x OUT_STRIDE

    int tid = threadIdx.x;
    int e0 = blockIdx.x * 32;
    if (tid < 32) {
        int e = e0 + tid;
        sSnd[tid] = eidx[e];
        sSh0[tid]     = eattr[(size_t)e*4 + 0];
        sSh1[tid*3+0] = eattr[(size_t)e*4 + 1];
        sSh1[tid*3+1] = eattr[(size_t)e*4 + 2];
        sSh1[tid*3+2] = eattr[(size_t)e*4 + 3];
    }
    __syncthreads();

    // Phase 1: build A fragments directly in mma layout
    for (int idx = tid; idx < 4096; idx += 768) {
        int el = idx >> 7, u = idx & 127;
        const float* up = g_UP + (size_t)sSnd[el] * 512;
        float ss = up[u];
        float vx = up[128+u], vy = up[256+u], vz = up[384+u];
        const float* tp = g_TPW + (size_t)(e0 + el) * 512;
        float w00 = tp[u], w01 = tp[128+u], w10 = tp[256+u], w11 = tp[384+u];
        float sh0 = sSh0[el];
        float h1x = sSh1[el*3+0], h1y = sSh1[el*3+1], h1z = sSh1[el*3+2];

        float a0v = K_A0 * w00 * ss * sh0;
        float b0v = K_B0 * w11 * (vx*h1x + vy*h1y + vz*h1z);
        float pv  = K_1  * w01 * ss;
        float t   = K_1  * w10 * sh0;

        int strip = el >> 4, row = el & 15;
        int r = row & 7, hi = row >> 3;
        int ks = u >> 3, kr = u & 7;
        int l = r*4 + (kr & 3), v = hi + ((kr >> 2) << 1);
        int off = l*4 + v;

        sA_S[(strip*32 + ks)*128 + off]        = f2tf_f(a0v);
        sA_S[(strip*32 + ks + 16)*128 + off]   = f2tf_f(b0v);
        sA_P[(strip*16 + ks)*128 + off]        = f2tf_f(pv);
        int bb = (strip*16 + ks)*128 + off;
        sA_B[bb]        = f2tf_f(t*vx);
        sA_B[bb + 4096] = f2tf_f(t*vy);
        sA_B[bb + 8192] = f2tf_f(t*vz);
    }
    __syncthreads();

    int wid = tid >> 5, lane = tid & 31;
    int r = lane >> 2, c2 = (lane & 3)*2;

    if (wid < 8) {
        // ---- S job: both strips, n-tiles {2*wid, 2*wid+1}, K=256 ----
        int np = wid;
        float acc[2][2][4];   // [strip][t][frag]
        #pragma unroll
        for (int s = 0; s < 2; s++)
            #pragma unroll
            for (int t = 0; t < 2; t++)
                #pragma unroll
                for (int i = 0; i < 4; i++) acc[s][t][i] = 0.f;

        #pragma unroll 4
        for (int k = 0; k < 32; k++) {
            float4 a0f = *(const float4*)(sA_S + k*128 + lane*4);          // strip 0
            float4 a1f = *(const float4*)(sA_S + (32 + k)*128 + lane*4);   // strip 1
            unsigned s0a = __float_as_uint(a0f.x), s0b = __float_as_uint(a0f.y);
            unsigned s0c = __float_as_uint(a0f.z), s0d = __float_as_uint(a0f.w);
            unsigned s1a = __float_as_uint(a1f.x), s1b = __float_as_uint(a1f.y);
            unsigned s1c = __float_as_uint(a1f.z), s1d = __float_as_uint(a1f.w);
            #pragma unroll
            for (int t = 0; t < 2; t++) {
                float2 bf = *(const float2*)(g_WSF + ((np*2 + t)*32 + k)*64 + lane*2);
                unsigned b0 = __float_as_uint(bf.x), b1 = __float_as_uint(bf.y);
                mma_tf32(acc[0][t], s0a, s0b, s0c, s0d, b0, b1);
                mma_tf32(acc[1][t], s1a, s1b, s1c, s1d, b0, b1);
            }
        }
        #pragma unroll
        for (int s = 0; s < 2; s++)
            #pragma unroll
            for (int t = 0; t < 2; t++) {
                int col = (np*2 + t)*8 + c2;
                int el = s*16 + r;
                *(float2*)&sOUT[el*OUT_STRIDE + col]     = make_float2(acc[s][t][0], acc[s][t][1]);
                *(float2*)&sOUT[(el+8)*OUT_STRIDE + col] = make_float2(acc[s][t][2], acc[s][t][3]);
            }
    } else {
        // ---- V job: P + Bx + By + Bz over 2 n-tiles, K=128 (16 ksteps) ----
        int j = wid - 8;
        int strip = j >> 3, np = j & 7;
        const float* ApP = sA_P + strip*16*128;
        const float* ApB = sA_B + strip*16*128;
        float aP[2][4], aX[2][4], aY[2][4], aZ[2][4];
        #pragma unroll
        for (int t = 0; t < 2; t++)
            #pragma unroll
            for (int i = 0; i < 4; i++) { aP[t][i]=0.f; aX[t][i]=0.f; aY[t][i]=0.f; aZ[t][i]=0.f; }

        #pragma unroll 4
        for (int k = 0; k < 16; k++) {
            float4 fP = *(const float4*)(ApP + k*128 + lane*4);
            float4 fX = *(const float4*)(ApB + k*128 + lane*4);
            float4 fY = *(const float4*)(ApB + 4096 + k*128 + lane*4);
            float4 fZ = *(const float4*)(ApB + 8192 + k*128 + lane*4);
            #pragma unroll
            for (int t = 0; t < 2; t++) {
                int nt = np*2 + t;
                float2 bT = *(const float2*)(g_WTF + (nt*16 + k)*64 + lane*2);
                float2 bB = *(const float2*)(g_WBF + (nt*16 + k)*64 + lane*2);
                unsigned bT0 = __float_as_uint(bT.x), bT1 = __float_as_uint(bT.y);
                unsigned bB0 = __float_as_uint(bB.x), bB1 = __float_as_uint(bB.y);
                mma_tf32(aP[t], __float_as_uint(fP.x), __float_as_uint(fP.y),
                                __float_as_uint(fP.z), __float_as_uint(fP.w), bT0, bT1);
                mma_tf32(aX[t], __float_as_uint(fX.x), __float_as_uint(fX.y),
                                __float_as_uint(fX.z), __float_as_uint(fX.w), bB0, bB1);
                mma_tf32(aY[t], __float_as_uint(fY.x), __float_as_uint(fY.y),
                                __float_as_uint(fY.z), __float_as_uint(fY.w), bB0, bB1);
                mma_tf32(aZ[t], __float_as_uint(fZ.x), __float_as_uint(fZ.y),
                                __float_as_uint(fZ.z), __float_as_uint(fZ.w), bB0, bB1);
            }
        }
        // recombine in registers, stage into sOUT: [el][128 + 3*col + i]
        #pragma unroll
        for (int t = 0; t < 2; t++) {
            int col = (np*2 + t)*8 + c2;
            #pragma unroll
            for (int half = 0; half < 2; half++) {
                int el = strip*16 + r + half*8;
                float shx = sSh1[el*3+0], shy = sSh1[el*3+1], shz = sSh1[el*3+2];
                float Q0 = aP[t][half*2], Q1 = aP[t][half*2+1];
                float X0 = aX[t][half*2], X1 = aX[t][half*2+1];
                float Y0 = aY[t][half*2], Y1 = aY[t][half*2+1];
                float Z0 = aZ[t][half*2], Z1 = aZ[t][half*2+1];
                float* o = sOUT + el*OUT_STRIDE + 128 + 3*col;
                *(float2*)(o)     = make_float2(Q0*shx + X0, Q0*shy + Y0);
                *(float2*)(o + 2) = make_float2(Q0*shz + Z0, Q1*shx + X1);
                *(float2*)(o + 4) = make_float2(Q1*shy + Y1, Q1*shz + Z1);
            }
        }
    }
    __syncthreads();

    // Phase 3: coalesced copy-out, 4096 float4s
    for (int idx = tid; idx < 4096; idx += 768) {
        int el = idx >> 7, q = idx & 127;
        float4 v = *(const float4*)&sOUT[el*OUT_STRIDE + q*4];
        *(float4*)&out[(size_t)(e0 + el)*512 + q*4] = v;
    }
}

// ---------------------------------------------------------------------------
extern "C" void kernel_launch(void* const* d_in, const int* in_sizes, int n_in,
                              void* d_out, int out_size) {
    const float* nf    = (const float*)d_in[0];
    const float* eattr = (const float*)d_in[1];
    const float* ef    = (const float*)d_in[2];
    const int*   eidx  = (const int*)d_in[3];
    const float* Wus   = (const float*)d_in[4];
    const float* Wuv   = (const float*)d_in[5];
    const float* w0    = (const float*)d_in[6];
    const float* w1    = (const float*)d_in[7];
    const float* w2    = (const float*)d_in[8];
    const float* w3    = (const float*)d_in[9];
    const float* Wos   = (const float*)d_in[10];
    const float* Wov   = (const float*)d_in[11];
    float* out = (float*)d_out;

    const size_t smem1 = 40960 * 4;   // 160KB
    const size_t smem3 = 41472 * 4;   // ~162KB
    cudaFuncSetAttribute(k_node_up,  cudaFuncAttributeMaxDynamicSharedMemorySize, (int)smem1);
    cudaFuncSetAttribute(k_edge_out, cudaFuncAttributeMaxDynamicSharedMemorySize, (int)smem3);

    k_prep    <<<64, 512>>>(w0, w1, w2, w3, Wos, Wov);
    k_node_up <<<N_NODES/16, 512, smem1>>>(nf, Wus, Wuv);
    k_edge_mlp<<<N_EDGES/32, 512>>>(ef);
    k_edge_out<<<N_EDGES/32, 768, smem3>>>(eattr, eidx, out);
}

// round 15
// speedup vs baseline: 1.1762x; 1.0055x over previous
#include <cuda_runtime.h>
#include <math.h>

#define N_NODES 20000
#define N_EDGES 100000

// Scratch (allowed: __device__ globals, no runtime allocation)
__device__ float g_UP[(size_t)N_NODES * 512];    // [n][c*128+u], c: 0=s,1=vx,2=vy,3=vz
__device__ float g_TPW[(size_t)N_EDGES * 512];   // [e][512]
// Pre-converted tf32 fragment-layout weights
__device__ float g_W0F[512];     // w0/sqrt(8):  [nt8][ks1][lane32][2]
__device__ float g_W1F[4096];    // w1/8:        [nt8][ks8][lane32][2]
__device__ float g_W2F[4096];    // w2/8:        [nt8][ks8][lane32][2]
__device__ float g_W3F[32768];   // w3/8:        [nt64][ks8][lane32][2]
__device__ float g_WSF[32768];   // Wos:         [nt16][ks32][lane32][2]
__device__ float g_WTF[16384];   // Wov top      [nt16][ks16][lane32][2]
__device__ float g_WBF[16384];   // Wov bot      [nt16][ks16][lane32][2]

#define INV_SQRT_MUL 0.08838834764831845f   // 1/sqrt(128)
#define SILU_NORM    1.6790390826f
#define K_A0 (0.7071067811865476f  * 0.0625f)   // PW_0E / sqrt(256)
#define K_B0 (0.40824829046386307f * 0.0625f)   // PW_0E*INV_SQRT3 / sqrt(256)
#define K_1  (0.7071067811865476f  * 0.0625f)   // PW_1O*INV_SQRT3 / sqrt(256)

#define OUT_STRIDE 520   // sOUT row stride (pad breaks STS bank conflicts)
#define A_STRIDE  132    // A-frag row stride: 132 mod 32 = 4 -> ks-groups hit
                         // distinct banks (was 128 -> 4-way STS conflicts).
                         // 132 floats = 528 B = 33*16 B, float4-aligned.

__device__ __forceinline__ float silu_act(float x) {
    return x * SILU_NORM / (1.0f + expf(-x));
}

__device__ __forceinline__ unsigned f2tf(float x) {
    unsigned u;
    asm("cvt.rna.tf32.f32 %0, %1;" : "=r"(u) : "f"(x));
    return u;
}
__device__ __forceinline__ float f2tf_f(float x) {
    return __uint_as_float(f2tf(x));
}

__device__ __forceinline__ void mma_tf32(float* c,
                                         unsigned a0, unsigned a1, unsigned a2, unsigned a3,
                                         unsigned b0, unsigned b1) {
    asm volatile("mma.sync.aligned.m16n8k8.row.col.f32.tf32.tf32.f32 "
                 "{%0,%1,%2,%3}, {%4,%5,%6,%7}, {%8,%9}, {%0,%1,%2,%3};"
                 : "+f"(c[0]), "+f"(c[1]), "+f"(c[2]), "+f"(c[3])
                 : "r"(a0), "r"(a1), "r"(a2), "r"(a3), "r"(b0), "r"(b1));
}

// silu(C-frag) -> A-fragment-layout smem store (128-stride buffers, K2 only).
__device__ __forceinline__ void silu_store_frag(float* buf, int strip, int nt,
                                                int r, int c2, const float* c) {
    int base = (strip*8 + nt)*128;
    int b2 = ((c2 >> 2) & 1) << 1;
    int la = r*4 + (c2 & 3);
    buf[base + la*4 + b2]           = f2tf_f(silu_act(c[0]));
    buf[base + (la+1)*4 + b2]       = f2tf_f(silu_act(c[1]));
    buf[base + la*4 + 1 + b2]       = f2tf_f(silu_act(c[2]));
    buf[base + (la+1)*4 + 1 + b2]   = f2tf_f(silu_act(c[3]));
}

// ---------------------------------------------------------------------------
// K0: one-time weight -> tf32 fragment-layout conversion
// ---------------------------------------------------------------------------
__global__ void k_prep(const float* __restrict__ w0,
                       const float* __restrict__ w1,
                       const float* __restrict__ w2,
                       const float* __restrict__ w3,
                       const float* __restrict__ Wos,
                       const float* __restrict__ Wov) {
    int tid = blockIdx.x * blockDim.x + threadIdx.x;
    int nth = gridDim.x * blockDim.x;
    for (int idx = tid; idx < 512; idx += nth) {
        int k = idx >> 6, n = idx & 63;
        int nt = n >> 3, l = (n & 7)*4 + (k & 3), v = (k >> 2) & 1;
        g_W0F[nt*64 + l*2 + v] = f2tf_f(w0[idx] * 0.35355339059327373f);
    }
    for (int idx = tid; idx < 4096; idx += nth) {
        int k = idx >> 6, n = idx & 63;
        int nt = n >> 3, l = (n & 7)*4 + (k & 3), v = (k >> 2) & 1;
        int a = (nt*8 + (k >> 3))*64 + l*2 + v;
        g_W1F[a] = f2tf_f(w1[idx] * 0.125f);
        g_W2F[a] = f2tf_f(w2[idx] * 0.125f);
    }
    for (int idx = tid; idx < 32768; idx += nth) {
        int k = idx >> 9, n = idx & 511;
        int nt = n >> 3, l = (n & 7)*4 + (k & 3), v = (k >> 2) & 1;
        g_W3F[(nt*8 + (k >> 3))*64 + l*2 + v] = f2tf_f(w3[idx] * 0.125f);
    }
    for (int idx = tid; idx < 32768; idx += nth) {
        int k = idx >> 7, n = idx & 127;
        int nt = n >> 3, l = (n & 7)*4 + (k & 3), v = (k >> 2) & 1;
        g_WSF[(nt*32 + (k >> 3))*64 + l*2 + v] = f2tf_f(Wos[idx]);
    }
    for (int idx = tid; idx < 16384; idx += nth) {
        int k = idx >> 7, n = idx & 127;
        int nt = n >> 3, l = (n & 7)*4 + (k & 3), v = (k >> 2) & 1;
        int a = (nt*16 + (k >> 3))*64 + l*2 + v;
        g_WTF[a] = f2tf_f(Wov[idx]);
        g_WBF[a] = f2tf_f(Wov[idx + 16384]);
    }
}

// ---------------------------------------------------------------------------
// K1: node up-projection (R7 scalar version).  16 nodes/block, 512 threads.
// ---------------------------------------------------------------------------
__global__ void __launch_bounds__(512) k_node_up(const float* __restrict__ nf,
                                                 const float* __restrict__ Wus,
                                                 const float* __restrict__ Wuv) {
    extern __shared__ float sm[];
    float* sWs = sm;            // 16384
    float* sWv = sm + 16384;    // 16384
    float* sA  = sm + 32768;    // 16*512 = 8192
    int tid = threadIdx.x;
    {
        const float4* src = (const float4*)Wus; float4* dst = (float4*)sWs;
        #pragma unroll
        for (int i = 0; i < 8; i++) dst[tid + i*512] = src[tid + i*512];
        src = (const float4*)Wuv; dst = (float4*)sWv;
        #pragma unroll
        for (int i = 0; i < 8; i++) dst[tid + i*512] = src[tid + i*512];
    }
    int n0 = blockIdx.x * 16;
    {
        const float4* src = (const float4*)(nf + (size_t)n0 * 512);
        float4* dst = (float4*)sA;
        #pragma unroll
        for (int i = 0; i < 4; i++) dst[tid + i*512] = src[tid + i*512];
    }
    __syncthreads();

    int w = tid & 127, g = tid >> 7;
    float acc[4][4];
    #pragma unroll
    for (int j = 0; j < 4; j++)
        #pragma unroll
        for (int c = 0; c < 4; c++) acc[j][c] = 0.f;

    for (int k = 0; k < 128; k += 4) {
        float ws[4], wv[4];
        #pragma unroll
        for (int kk = 0; kk < 4; kk++) { ws[kk] = sWs[(k+kk)*128 + w]; wv[kk] = sWv[(k+kk)*128 + w]; }
        #pragma unroll
        for (int j = 0; j < 4; j++) {
            int base = (g*4 + j) * 512;
            float4 sa = *(const float4*)&sA[base + k];
            acc[j][0] += sa.x*ws[0] + sa.y*ws[1] + sa.z*ws[2] + sa.w*ws[3];
            float4 va = *(const float4*)&sA[base + 128 + 3*k];
            float4 vb = *(const float4*)&sA[base + 128 + 3*k + 4];
            float4 vc = *(const float4*)&sA[base + 128 + 3*k + 8];
            acc[j][1] += va.x*wv[0] + va.w*wv[1] + vb.z*wv[2] + vc.y*wv[3];
            acc[j][2] += va.y*wv[0] + vb.x*wv[1] + vb.w*wv[2] + vc.z*wv[3];
            acc[j][3] += va.z*wv[0] + vb.y*wv[1] + vc.x*wv[2] + vc.w*wv[3];
        }
    }
    #pragma unroll
    for (int j = 0; j < 4; j++) {
        int n = n0 + g*4 + j;
        float* o = g_UP + (size_t)n * 512;
        o[w]       = acc[j][0] * INV_SQRT_MUL;
        o[128 + w] = acc[j][1] * INV_SQRT_MUL;
        o[256 + w] = acc[j][2] * INV_SQRT_MUL;
        o[384 + w] = acc[j][3] * INV_SQRT_MUL;
    }
}

// ---------------------------------------------------------------------------
// K2 v2: edge MLP fully on tensor cores. 32 edges/block, 512 threads (16 warps).
// ---------------------------------------------------------------------------
__global__ void __launch_bounds__(512) k_edge_mlp(const float* __restrict__ ef) {
    __shared__ float sF0[256];     // layer-0 A frags (K=8: 1 kstep, 2 strips)
    __shared__ float bufA[2048];   // [strip2][ks8][128]
    __shared__ float bufB[2048];
    int tid = threadIdx.x;
    int wid = tid >> 5, lane = tid & 31;
    int e0 = blockIdx.x * 32;

    // Build layer-0 A fragments straight from ef
    if (tid < 256) {
        float val = ef[(size_t)e0*8 + tid];
        int el = tid >> 3, k = tid & 7;
        int strip = el >> 4, row = el & 15;
        int r = row & 7, hi = row >> 3;
        int l = r*4 + (k & 3), v = hi + ((k >> 2) << 1);
        sF0[strip*128 + l*4 + v] = f2tf_f(val);
    }
    __syncthreads();

    int strip = wid & 1, nt = wid >> 1;
    int r = lane >> 2, c2 = (lane & 3)*2;

    // Layer 0: (32x8)@(8x64), 1 mma per warp -> bufA
    {
        float c[4] = {0.f, 0.f, 0.f, 0.f};
        float4 af = *(const float4*)(sF0 + strip*128 + lane*4);
        float2 bf = *(const float2*)(g_W0F + nt*64 + lane*2);
        mma_tf32(c, __float_as_uint(af.x), __float_as_uint(af.y),
                    __float_as_uint(af.z), __float_as_uint(af.w),
                    __float_as_uint(bf.x), __float_as_uint(bf.y));
        silu_store_frag(bufA, strip, nt, r, c2, c);
    }
    __syncthreads();

    // Layer 1: (32x64)@(64x64), 8 mmas per warp, bufA -> bufB
    {
        float c[4] = {0.f, 0.f, 0.f, 0.f};
        #pragma unroll
        for (int ks = 0; ks < 8; ks++) {
            float4 af = *(const float4*)(bufA + (strip*8 + ks)*128 + lane*4);
            float2 bf = *(const float2*)(g_W1F + (nt*8 + ks)*64 + lane*2);
            mma_tf32(c, __float_as_uint(af.x), __float_as_uint(af.y),
                        __float_as_uint(af.z), __float_as_uint(af.w),
                        __float_as_uint(bf.x), __float_as_uint(bf.y));
        }
        silu_store_frag(bufB, strip, nt, r, c2, c);
    }
    __syncthreads();

    // Layer 2: bufB -> bufA
    {
        float c[4] = {0.f, 0.f, 0.f, 0.f};
        #pragma unroll
        for (int ks = 0; ks < 8; ks++) {
            float4 af = *(const float4*)(bufB + (strip*8 + ks)*128 + lane*4);
            float2 bf = *(const float2*)(g_W2F + (nt*8 + ks)*64 + lane*2);
            mma_tf32(c, __float_as_uint(af.x), __float_as_uint(af.y),
                        __float_as_uint(af.z), __float_as_uint(af.w),
                        __float_as_uint(bf.x), __float_as_uint(bf.y));
        }
        silu_store_frag(bufA, strip, nt, r, c2, c);
    }
    __syncthreads();

    // Final: tpw = h @ (w3/8); 16 warps: (strip, 8 n-tiles of 64) -> g_TPW
    {
        int nb = (wid >> 1) * 8;
        float acc[8][4];
        #pragma unroll
        for (int t = 0; t < 8; t++)
            #pragma unroll
            for (int i = 0; i < 4; i++) acc[t][i] = 0.f;
        #pragma unroll
        for (int kk = 0; kk < 8; kk++) {
            float4 af = *(const float4*)(bufA + (strip*8 + kk)*128 + lane*4);
            unsigned a0 = __float_as_uint(af.x), a1 = __float_as_uint(af.y);
            unsigned a2 = __float_as_uint(af.z), a3 = __float_as_uint(af.w);
            #pragma unroll
            for (int t = 0; t < 8; t++) {
                float2 bf = *(const float2*)(g_W3F + ((nb + t)*8 + kk)*64 + lane*2);
                mma_tf32(acc[t], a0, a1, a2, a3, __float_as_uint(bf.x), __float_as_uint(bf.y));
            }
        }
        #pragma unroll
        for (int t = 0; t < 8; t++) {
            int col = (nb + t)*8 + c2;
            size_t eA = (size_t)(e0 + strip*16 + r);
            *(float2*)&g_TPW[eA*512 + col]     = make_float2(acc[t][0], acc[t][1]);
            *(float2*)&g_TPW[(eA+8)*512 + col] = make_float2(acc[t][2], acc[t][3]);
        }
    }
}

// ---------------------------------------------------------------------------
// K3 v7: R11 structure + padded A-frag stride (132) to kill phase-1 STS
// bank conflicts. 32 edges/block, 768 threads (24 warps), 24 jobs.
// smem floats: sA_S 0..8448 | sA_P 8448..12672 | sA_B 12672..25344
//              meta 25344..25504 | sOUT 25600..42240 (32x520)
// ---------------------------------------------------------------------------
__global__ void __launch_bounds__(768) k_edge_out(const float* __restrict__ eattr,
                                                  const int* __restrict__ eidx,
                                                  float* __restrict__ out) {
    extern __shared__ float sm[];
    float* sA_S = sm;                    // 64 rows x A_STRIDE
    float* sA_P = sm + 8448;             // 32 rows
    float* sA_B = sm + 12672;            // 3 comps x 32 rows
    float* sSh0 = sm + 25344;
    float* sSh1 = sm + 25376;
    int*   sSnd = (int*)(sm + 25472);
    float* sOUT = sm + 25600;            // 32 rows x OUT_STRIDE

    const int BCOMP = 32 * A_STRIDE;     // 4224: sA_B comp stride

    int tid = threadIdx.x;
    int e0 = blockIdx.x * 32;
    if (tid < 32) {
        int e = e0 + tid;
        sSnd[tid] = eidx[e];
        sSh0[tid]     = eattr[(size_t)e*4 + 0];
        sSh1[tid*3+0] = eattr[(size_t)e*4 + 1];
        sSh1[tid*3+1] = eattr[(size_t)e*4 + 2];
        sSh1[tid*3+2] = eattr[(size_t)e*4 + 3];
    }
    __syncthreads();

    // Phase 1: build A fragments directly in mma layout (padded rows)
    for (int idx = tid; idx < 4096; idx += 768) {
        int el = idx >> 7, u = idx & 127;
        const float* up = g_UP + (size_t)sSnd[el] * 512;
        float ss = up[u];
        float vx = up[128+u], vy = up[256+u], vz = up[384+u];
        const float* tp = g_TPW + (size_t)(e0 + el) * 512;
        float w00 = tp[u], w01 = tp[128+u], w10 = tp[256+u], w11 = tp[384+u];
        float sh0 = sSh0[el];
        float h1x = sSh1[el*3+0], h1y = sSh1[el*3+1], h1z = sSh1[el*3+2];

        float a0v = K_A0 * w00 * ss * sh0;
        float b0v = K_B0 * w11 * (vx*h1x + vy*h1y + vz*h1z);
        float pv  = K_1  * w01 * ss;
        float t   = K_1  * w10 * sh0;

        int strip = el >> 4, row = el & 15;
        int r = row & 7, hi = row >> 3;
        int ks = u >> 3, kr = u & 7;
        int l = r*4 + (kr & 3), v = hi + ((kr >> 2) << 1);
        int off = l*4 + v;

        sA_S[(strip*32 + ks)*A_STRIDE + off]        = f2tf_f(a0v);
        sA_S[(strip*32 + ks + 16)*A_STRIDE + off]   = f2tf_f(b0v);
        sA_P[(strip*16 + ks)*A_STRIDE + off]        = f2tf_f(pv);
        int bb = (strip*16 + ks)*A_STRIDE + off;
        sA_B[bb]            = f2tf_f(t*vx);
        sA_B[bb + BCOMP]    = f2tf_f(t*vy);
        sA_B[bb + 2*BCOMP]  = f2tf_f(t*vz);
    }
    __syncthreads();

    int wid = tid >> 5, lane = tid & 31;
    int r = lane >> 2, c2 = (lane & 3)*2;

    if (wid < 8) {
        // ---- S job: both strips, n-tiles {2*wid, 2*wid+1}, K=256 ----
        int np = wid;
        float acc[2][2][4];   // [strip][t][frag]
        #pragma unroll
        for (int s = 0; s < 2; s++)
            #pragma unroll
            for (int t = 0; t < 2; t++)
                #pragma unroll
                for (int i = 0; i < 4; i++) acc[s][t][i] = 0.f;

        #pragma unroll 4
        for (int k = 0; k < 32; k++) {
            float4 a0f = *(const float4*)(sA_S + k*A_STRIDE + lane*4);          // strip 0
            float4 a1f = *(const float4*)(sA_S + (32 + k)*A_STRIDE + lane*4);   // strip 1
            unsigned s0a = __float_as_uint(a0f.x), s0b = __float_as_uint(a0f.y);
            unsigned s0c = __float_as_uint(a0f.z), s0d = __float_as_uint(a0f.w);
            unsigned s1a = __float_as_uint(a1f.x), s1b = __float_as_uint(a1f.y);
            unsigned s1c = __float_as_uint(a1f.z), s1d = __float_as_uint(a1f.w);
            #pragma unroll
            for (int t = 0; t < 2; t++) {
                float2 bf = *(const float2*)(g_WSF + ((np*2 + t)*32 + k)*64 + lane*2);
                unsigned b0 = __float_as_uint(bf.x), b1 = __float_as_uint(bf.y);
                mma_tf32(acc[0][t], s0a, s0b, s0c, s0d, b0, b1);
                mma_tf32(acc[1][t], s1a, s1b, s1c, s1d, b0, b1);
            }
        }
        #pragma unroll
        for (int s = 0; s < 2; s++)
            #pragma unroll
            for (int t = 0; t < 2; t++) {
                int col = (np*2 + t)*8 + c2;
                int el = s*16 + r;
                *(float2*)&sOUT[el*OUT_STRIDE + col]     = make_float2(acc[s][t][0], acc[s][t][1]);
                *(float2*)&sOUT[(el+8)*OUT_STRIDE + col] = make_float2(acc[s][t][2], acc[s][t][3]);
            }
    } else {
        // ---- V job: P + Bx + By + Bz over 2 n-tiles, K=128 (16 ksteps) ----
        int j = wid - 8;
        int strip = j >> 3, np = j & 7;
        const float* ApP = sA_P + strip*16*A_STRIDE;
        const float* ApB = sA_B + strip*16*A_STRIDE;
        float aP[2][4], aX[2][4], aY[2][4], aZ[2][4];
        #pragma unroll
        for (int t = 0; t < 2; t++)
            #pragma unroll
            for (int i = 0; i < 4; i++) { aP[t][i]=0.f; aX[t][i]=0.f; aY[t][i]=0.f; aZ[t][i]=0.f; }

        #pragma unroll 4
        for (int k = 0; k < 16; k++) {
            float4 fP = *(const float4*)(ApP + k*A_STRIDE + lane*4);
            float4 fX = *(const float4*)(ApB + k*A_STRIDE + lane*4);
            float4 fY = *(const float4*)(ApB + BCOMP + k*A_STRIDE + lane*4);
            float4 fZ = *(const float4*)(ApB + 2*BCOMP + k*A_STRIDE + lane*4);
            #pragma unroll
            for (int t = 0; t < 2; t++) {
                int nt = np*2 + t;
                float2 bT = *(const float2*)(g_WTF + (nt*16 + k)*64 + lane*2);
                float2 bB = *(const float2*)(g_WBF + (nt*16 + k)*64 + lane*2);
                unsigned bT0 = __float_as_uint(bT.x), bT1 = __float_as_uint(bT.y);
                unsigned bB0 = __float_as_uint(bB.x), bB1 = __float_as_uint(bB.y);
                mma_tf32(aP[t], __float_as_uint(fP.x), __float_as_uint(fP.y),
                                __float_as_uint(fP.z), __float_as_uint(fP.w), bT0, bT1);
                mma_tf32(aX[t], __float_as_uint(fX.x), __float_as_uint(fX.y),
                                __float_as_uint(fX.z), __float_as_uint(fX.w), bB0, bB1);
                mma_tf32(aY[t], __float_as_uint(fY.x), __float_as_uint(fY.y),
                                __float_as_uint(fY.z), __float_as_uint(fY.w), bB0, bB1);
                mma_tf32(aZ[t], __float_as_uint(fZ.x), __float_as_uint(fZ.y),
                                __float_as_uint(fZ.z), __float_as_uint(fZ.w), bB0, bB1);
            }
        }
        // recombine in registers, stage into sOUT: [el][128 + 3*col + i]
        #pragma unroll
        for (int t = 0; t < 2; t++) {
            int col = (np*2 + t)*8 + c2;
            #pragma unroll
            for (int half = 0; half < 2; half++) {
                int el = strip*16 + r + half*8;
                float shx = sSh1[el*3+0], shy = sSh1[el*3+1], shz = sSh1[el*3+2];
                float Q0 = aP[t][half*2], Q1 = aP[t][half*2+1];
                float X0 = aX[t][half*2], X1 = aX[t][half*2+1];
                float Y0 = aY[t][half*2], Y1 = aY[t][half*2+1];
                float Z0 = aZ[t][half*2], Z1 = aZ[t][half*2+1];
                float* o = sOUT + el*OUT_STRIDE + 128 + 3*col;
                *(float2*)(o)     = make_float2(Q0*shx + X0, Q0*shy + Y0);
                *(float2*)(o + 2) = make_float2(Q0*shz + Z0, Q1*shx + X1);
                *(float2*)(o + 4) = make_float2(Q1*shy + Y1, Q1*shz + Z1);
            }
        }
    }
    __syncthreads();

    // Phase 3: coalesced copy-out, 4096 float4s
    for (int idx = tid; idx < 4096; idx += 768) {
        int el = idx >> 7, q = idx & 127;
        float4 v = *(const float4*)&sOUT[el*OUT_STRIDE + q*4];
        *(float4*)&out[(size_t)(e0 + el)*512 + q*4] = v;
    }
}

// ---------------------------------------------------------------------------
extern "C" void kernel_launch(void* const* d_in, const int* in_sizes, int n_in,
                              void* d_out, int out_size) {
    const float* nf    = (const float*)d_in[0];
    const float* eattr = (const float*)d_in[1];
    const float* ef    = (const float*)d_in[2];
    const int*   eidx  = (const int*)d_in[3];
    const float* Wus   = (const float*)d_in[4];
    const float* Wuv   = (const float*)d_in[5];
    const float* w0    = (const float*)d_in[6];
    const float* w1    = (const float*)d_in[7];
    const float* w2    = (const float*)d_in[8];
    const float* w3    = (const float*)d_in[9];
    const float* Wos   = (const float*)d_in[10];
    const float* Wov   = (const float*)d_in[11];
    float* out = (float*)d_out;

    const size_t smem1 = 40960 * 4;   // 160KB
    const size_t smem3 = 42240 * 4;   // ~165KB
    cudaFuncSetAttribute(k_node_up,  cudaFuncAttributeMaxDynamicSharedMemorySize, (int)smem1);
    cudaFuncSetAttribute(k_edge_out, cudaFuncAttributeMaxDynamicSharedMemorySize, (int)smem3);

    k_prep    <<<64, 512>>>(w0, w1, w2, w3, Wos, Wov);
    k_node_up <<<N_NODES/16, 512, smem1>>>(nf, Wus, Wuv);
    k_edge_mlp<<<N_EDGES/32, 512>>>(ef);
    k_edge_out<<<N_EDGES/32, 768, smem3>>>(eattr, eidx, out);
}